// round 9
// baseline (speedup 1.0000x reference)
#include <cuda_runtime.h>
#include <cuda_fp16.h>
#include <cstdint>

#define NN 50000
#define EE 800000
#define RR 3
#define DD 128
#define HH 4
#define MSEG (RR * NN)            // 150000 segments, keyed seg = dst*RR + r
#define SCAN_BLK 1024
#define NSB ((MSEG + SCAN_BLK - 1) / SCAN_BLK)   // 147

// ---------------- scratch (device globals) --------------------------------------
__device__ __align__(16) __half g_hh[(size_t)RR * NN * DD]; // fp16 features
__device__ float g_asrc[RR * NN * HH];
__device__ float g_adst[RR * NN * HH];
__device__ float g_gw[RR];
__device__ float g_biasf[DD];
__device__ int   g_cnt[MSEG];
__device__ int   g_off[MSEG];
__device__ int   g_cur[MSEG];
__device__ int   g_bsum[256];
__device__ int   g_esrc[RR * EE];

// ---------------- packed fp32x2 helpers -----------------------------------------
#define PACK_DUP(d, f) asm("mov.b64 %0, {%1, %2};" : "=l"(d) : "f"(f), "f"(f))
#define FMA2(d, a, b, c) \
    asm("fma.rn.f32x2 %0, %1, %2, %3;" : "=l"(d) : "l"(a), "l"(b), "l"(c))

// ---------------- K0: gate softmax + fused bias ---------------------------------
__global__ void k_prep(const float* __restrict__ gate,
                       const float* __restrict__ bias,
                       float* __restrict__ out_gw) {
    __shared__ float gw[RR];
    int d = threadIdx.x;  // 128
    if (d == 0) {
        float m = gate[0];
        for (int r = 1; r < RR; r++) m = fmaxf(m, gate[r]);
        float e[RR], s = 0.f;
        for (int r = 0; r < RR; r++) { e[r] = expf(gate[r] - m); s += e[r]; }
        for (int r = 0; r < RR; r++) {
            gw[r] = e[r] / s;
            g_gw[r] = gw[r];
            out_gw[r] = gw[r];
        }
    }
    __syncthreads();
    float b = 0.f;
    for (int r = 0; r < RR; r++) b += gw[r] * bias[r * DD + d];
    g_biasf[d] = b;
}

// ---------------- K1: zero degree counts ----------------------------------------
__global__ void k_init() {
    int i = blockIdx.x * blockDim.x + threadIdx.x;
    if (i < MSEG / 4) ((int4*)g_cnt)[i] = make_int4(0, 0, 0, 0);
}

// ---------------- K2: GEMM h_r = x @ W_r (fp32x2, dup-free mainloop) -------------
#define BM 128
#define BK 32
#define SMEM_X2  (BK * BM * 8)                         // 32768: Xs2 dup pairs
#define SMEM_W   (BK * DD * 4)                         // 16384: Ws floats
#define GEMM_SMEM (SMEM_X2 + SMEM_W + 2 * DD * 4)      // + as/ad

__global__ void __launch_bounds__(256, 2)
k_gemm(const float* __restrict__ x, const float* __restrict__ W,
       const float* __restrict__ att_src, const float* __restrict__ att_dst) {
    extern __shared__ char smem[];
    unsigned long long* Xs2 = (unsigned long long*)smem;       // [BK][BM] (a,a)
    float* Ws   = (float*)(smem + SMEM_X2);                    // [BK][DD]
    float* as_s = (float*)(smem + SMEM_X2 + SMEM_W);
    float* ad_s = as_s + DD;

    const int r = blockIdx.y;
    const int row0 = blockIdx.x * BM;
    const int tid = threadIdx.x;
    const int tx = tid & 15;       // col group (8 cols)
    const int ty = tid >> 4;       // row group (8 rows)
    const float* Wr = W + (size_t)r * DD * DD;

    if (tid < DD) {
        as_s[tid] = __ldg(&att_src[r * DD + tid]);
        ad_s[tid] = __ldg(&att_dst[r * DD + tid]);
    }

    // acc[p][cp]: row ty*8+p, column pair (tx*8+2cp, tx*8+2cp+1)
    unsigned long long acc[8][4];
#pragma unroll
    for (int p = 0; p < 8; p++)
#pragma unroll
        for (int cp = 0; cp < 4; cp++) acc[p][cp] = 0ULL;

    const int lrow = tid >> 1;           // 0..127
    const int lk = (tid & 1) * 16;       // 0 or 16

    for (int k0 = 0; k0 < DD; k0 += BK) {
        const int grow = row0 + lrow;
#pragma unroll
        for (int q = 0; q < 4; q++) {
            int kk = lk + q * 4;
            float4 v = make_float4(0.f, 0.f, 0.f, 0.f);
            if (grow < NN) v = *(const float4*)&x[(size_t)grow * DD + k0 + kk];
            unsigned long long p0, p1, p2, p3;
            PACK_DUP(p0, v.x); PACK_DUP(p1, v.y);
            PACK_DUP(p2, v.z); PACK_DUP(p3, v.w);
            Xs2[(kk + 0) * BM + lrow] = p0;
            Xs2[(kk + 1) * BM + lrow] = p1;
            Xs2[(kk + 2) * BM + lrow] = p2;
            Xs2[(kk + 3) * BM + lrow] = p3;
        }
#pragma unroll
        for (int q = 0; q < 4; q++) {
            int lin = q * 1024 + tid * 4;
            *(float4*)&Ws[lin] = *(const float4*)&Wr[(size_t)k0 * DD + lin];
        }
        __syncthreads();

#pragma unroll 8
        for (int kk = 0; kk < BK; kk++) {
            const unsigned long long* ap = &Xs2[kk * BM + ty * 8];
            ulonglong2 a01 = *(const ulonglong2*)(ap + 0);
            ulonglong2 a23 = *(const ulonglong2*)(ap + 2);
            ulonglong2 a45 = *(const ulonglong2*)(ap + 4);
            ulonglong2 a67 = *(const ulonglong2*)(ap + 6);
            unsigned long long av[8] = {a01.x, a01.y, a23.x, a23.y,
                                        a45.x, a45.y, a67.x, a67.y};
            // B pairs: consecutive cols straight from Ws
            ulonglong2 bp01 = *(const ulonglong2*)&Ws[kk * DD + tx * 8];
            ulonglong2 bp23 = *(const ulonglong2*)&Ws[kk * DD + tx * 8 + 4];
#pragma unroll
            for (int p = 0; p < 8; p++) {
                FMA2(acc[p][0], av[p], bp01.x, acc[p][0]);
                FMA2(acc[p][1], av[p], bp01.y, acc[p][1]);
                FMA2(acc[p][2], av[p], bp23.x, acc[p][2]);
                FMA2(acc[p][3], av[p], bp23.y, acc[p][3]);
            }
        }
        __syncthreads();
    }

    // ---- epilogue: fp16 store + fused attention-logit dots -----------------------
    const int head = tx >> 2;
    float asv[8], adv[8];
#pragma unroll
    for (int j = 0; j < 8; j++) {
        asv[j] = as_s[tx * 8 + j];
        adv[j] = ad_s[tx * 8 + j];
    }

#pragma unroll
    for (int p = 0; p < 8; p++) {
        int grow = row0 + ty * 8 + p;
        float c[8];
#pragma unroll
        for (int cp = 0; cp < 4; cp++) {
            float2 v = *(float2*)&acc[p][cp];
            c[2 * cp] = v.x;
            c[2 * cp + 1] = v.y;
        }
        float ps = 0.f, pd = 0.f;
#pragma unroll
        for (int j = 0; j < 8; j++) {
            ps += c[j] * asv[j];
            pd += c[j] * adv[j];
        }
#pragma unroll
        for (int o = 1; o <= 2; o <<= 1) {
            ps += __shfl_xor_sync(0xffffffffu, ps, o);
            pd += __shfl_xor_sync(0xffffffffu, pd, o);
        }
        __half2 oh[4];
#pragma unroll
        for (int j = 0; j < 4; j++)
            oh[j] = __floats2half2_rn(c[2 * j], c[2 * j + 1]);
        if (grow < NN) {
            *(uint4*)&g_hh[((size_t)r * NN + grow) * DD + tx * 8] = *(uint4*)oh;
            if ((tx & 3) == 0) {
                g_asrc[((size_t)r * NN + grow) * HH + head] = ps;
                g_adst[((size_t)r * NN + grow) * HH + head] = pd;
            }
        }
    }
}

// ---------------- K4a: degree histogram (seg = dst*RR + r) -----------------------
__global__ void k_hist(const int* __restrict__ ei) {
    int e = blockIdx.x * blockDim.x + threadIdx.x;
    int r = blockIdx.y;
    if (e >= EE) return;
    int dst = __ldg(&ei[r * 2 * EE + EE + e]);
    atomicAdd(&g_cnt[dst * RR + r], 1);
}

// ---------------- K4b: scan stage 1 — per-block sums ------------------------------
__global__ void k_scan_a() {
    __shared__ int ws[8];
    int tid = threadIdx.x;
    int base = blockIdx.x * SCAN_BLK + tid * 4;
    int s = 0;
#pragma unroll
    for (int k = 0; k < 4; k++) {
        int idx = base + k;
        if (idx < MSEG) s += g_cnt[idx];
    }
#pragma unroll
    for (int o = 16; o >= 1; o >>= 1) s += __shfl_xor_sync(0xffffffffu, s, o);
    if ((tid & 31) == 0) ws[tid >> 5] = s;
    __syncthreads();
    if (tid == 0) {
        int t = 0;
        for (int i = 0; i < 8; i++) t += ws[i];
        g_bsum[blockIdx.x] = t;
    }
}

// ---------------- K4c: scan stage 2 — offsets (block prefix in-kernel) ------------
__global__ void k_scan_c() {
    __shared__ int ws[8];
    __shared__ int blk_base;
    int tid = threadIdx.x;
    int lane = tid & 31, warp = tid >> 5;

    {
        int s = 0;
        for (int i = tid; i < blockIdx.x; i += 256) s += g_bsum[i];
#pragma unroll
        for (int o = 16; o >= 1; o >>= 1) s += __shfl_xor_sync(0xffffffffu, s, o);
        if (lane == 0) ws[warp] = s;
        __syncthreads();
        if (tid == 0) {
            int t = 0;
            for (int i = 0; i < 8; i++) t += ws[i];
            blk_base = t;
        }
        __syncthreads();
    }

    int base = blockIdx.x * SCAN_BLK + tid * 4;
    int c[4];
#pragma unroll
    for (int k = 0; k < 4; k++) {
        int idx = base + k;
        c[k] = (idx < MSEG) ? g_cnt[idx] : 0;
    }
    int t = c[0] + c[1] + c[2] + c[3];
    int inc = t;
#pragma unroll
    for (int o = 1; o < 32; o <<= 1) {
        int v = __shfl_up_sync(0xffffffffu, inc, o);
        if (lane >= o) inc += v;
    }
    if (lane == 31) ws[warp] = inc;
    __syncthreads();
    if (tid == 0) {
        int run = 0;
        for (int i = 0; i < 8; i++) { int v = ws[i]; ws[i] = run; run += v; }
    }
    __syncthreads();
    int ex = inc - t + ws[warp] + blk_base;
#pragma unroll
    for (int k = 0; k < 4; k++) {
        int idx = base + k;
        if (idx < MSEG) { g_off[idx] = ex; g_cur[idx] = ex; }
        ex += c[k];
    }
}

// ---------------- K4e: scatter edges into CSR ------------------------------------
__global__ void k_scatter(const int* __restrict__ ei) {
    int e = blockIdx.x * blockDim.x + threadIdx.x;
    int r = blockIdx.y;
    if (e >= EE) return;
    int src = __ldg(&ei[r * 2 * EE + e]);
    int dst = __ldg(&ei[r * 2 * EE + EE + e]);
    int pos = atomicAdd(&g_cur[dst * RR + r], 1);
    g_esrc[pos] = src;
}

// ---------------- K5: fused aggregation + residual + LayerNorm (warp per dst) ----
__global__ void __launch_bounds__(256)
k_agg(const float* __restrict__ x,
      const float* __restrict__ gamma,
      const float* __restrict__ beta,
      float* __restrict__ out) {
    int dst = (blockIdx.x * blockDim.x + threadIdx.x) >> 5;
    int lane = threadIdx.x & 31;
    if (dst >= NN) return;
    int head = lane >> 3;
    int c4 = lane * 4;

    float4 xv = __ldg((const float4*)&x[(size_t)dst * DD + c4]);
    float4 bf = *(const float4*)&g_biasf[c4];
    float4 acc = make_float4(xv.x + bf.x, xv.y + bf.y, xv.z + bf.z, xv.w + bf.w);

#pragma unroll
    for (int r = 0; r < RR; r++) {
        int seg = dst * RR + r;
        int beg = g_off[seg];
        int end = g_cur[seg];
        if (beg == end) continue;

        float adv = g_adst[((size_t)r * NN + dst) * HH + head];
        const __half* hr = g_hh + (size_t)r * NN * DD;
        const float* ar = g_asrc + (size_t)r * NN * HH;

        float denom = 0.f;
        float4 part = make_float4(0.f, 0.f, 0.f, 0.f);

        int i = beg;
        for (; i + 4 <= end; i += 4) {
            int s0 = __ldg(&g_esrc[i]);
            int s1 = __ldg(&g_esrc[i + 1]);
            int s2 = __ldg(&g_esrc[i + 2]);
            int s3 = __ldg(&g_esrc[i + 3]);
            float a0 = __ldg(&ar[s0 * HH + head]);
            float a1 = __ldg(&ar[s1 * HH + head]);
            float a2 = __ldg(&ar[s2 * HH + head]);
            float a3 = __ldg(&ar[s3 * HH + head]);
            uint2 h0 = __ldg((const uint2*)&hr[(size_t)s0 * DD + c4]);
            uint2 h1 = __ldg((const uint2*)&hr[(size_t)s1 * DD + c4]);
            uint2 h2 = __ldg((const uint2*)&hr[(size_t)s2 * DD + c4]);
            uint2 h3 = __ldg((const uint2*)&hr[(size_t)s3 * DD + c4]);
            float va[4] = {a0 + adv, a1 + adv, a2 + adv, a3 + adv};
            uint2 hv[4] = {h0, h1, h2, h3};
#pragma unroll
            for (int q = 0; q < 4; q++) {
                float v = va[q];
                v = v >= 0.f ? v : 0.2f * v;
                float w = __expf(v);
                denom += w;
                float2 f0 = __half22float2(*(__half2*)&hv[q].x);
                float2 f1 = __half22float2(*(__half2*)&hv[q].y);
                part.x += w * f0.x; part.y += w * f0.y;
                part.z += w * f1.x; part.w += w * f1.y;
            }
        }
        for (; i < end; i++) {
            int src = __ldg(&g_esrc[i]);
            float asv = __ldg(&ar[src * HH + head]);
            float v = asv + adv;
            v = v >= 0.f ? v : 0.2f * v;
            float w = __expf(v);
            denom += w;
            uint2 hv = __ldg((const uint2*)&hr[(size_t)src * DD + c4]);
            float2 f0 = __half22float2(*(__half2*)&hv.x);
            float2 f1 = __half22float2(*(__half2*)&hv.y);
            part.x += w * f0.x; part.y += w * f0.y;
            part.z += w * f1.x; part.w += w * f1.y;
        }
        float scale = g_gw[r] / (denom + 1e-16f);
        acc.x += scale * part.x; acc.y += scale * part.y;
        acc.z += scale * part.z; acc.w += scale * part.w;
    }

    float s = acc.x + acc.y + acc.z + acc.w;
    float q = acc.x * acc.x + acc.y * acc.y + acc.z * acc.z + acc.w * acc.w;
#pragma unroll
    for (int o = 16; o >= 1; o >>= 1) {
        s += __shfl_xor_sync(0xffffffffu, s, o);
        q += __shfl_xor_sync(0xffffffffu, q, o);
    }
    float mu = s * (1.f / DD);
    float var = q * (1.f / DD) - mu * mu;
    float rstd = rsqrtf(var + 1e-5f);
    float4 g = __ldg((const float4*)&gamma[c4]);
    float4 b = __ldg((const float4*)&beta[c4]);
    float4 o4;
    o4.x = (acc.x - mu) * rstd * g.x + b.x;
    o4.y = (acc.y - mu) * rstd * g.y + b.y;
    o4.z = (acc.z - mu) * rstd * g.z + b.z;
    o4.w = (acc.w - mu) * rstd * g.w + b.w;
    *(float4*)&out[(size_t)dst * DD + c4] = o4;
}

// ---------------- launch ------------------------------------------------------------
extern "C" void kernel_launch(void* const* d_in, const int* in_sizes, int n_in,
                              void* d_out, int out_size) {
    const float* x       = (const float*)d_in[0];
    const int*   ei      = (const int*)d_in[1];
    const float* W       = (const float*)d_in[3];
    const float* att_src = (const float*)d_in[4];
    const float* att_dst = (const float*)d_in[5];
    const float* bias    = (const float*)d_in[6];
    const float* gate    = (const float*)d_in[7];
    const float* gamma   = (const float*)d_in[8];
    const float* beta    = (const float*)d_in[9];
    float* out = (float*)d_out;

    static cudaStream_t s2 = nullptr;
    static cudaEvent_t evFork = nullptr, evJoin = nullptr;
    if (s2 == nullptr) {
        cudaStreamCreateWithFlags(&s2, cudaStreamNonBlocking);
        cudaEventCreateWithFlags(&evFork, cudaEventDisableTiming);
        cudaEventCreateWithFlags(&evJoin, cudaEventDisableTiming);
        cudaFuncSetAttribute(k_gemm, cudaFuncAttributeMaxDynamicSharedMemorySize, GEMM_SMEM);
    }

    // fork: CSR-build + prep branch runs concurrently with the GEMM branch
    cudaEventRecord(evFork, 0);
    cudaStreamWaitEvent(s2, evFork, 0);

    // ---- branch B (stream s2): prep + CSR build ----
    k_prep<<<1, DD, 0, s2>>>(gate, bias, out + (out_size - RR));
    k_init<<<(MSEG / 4 + 255) / 256, 256, 0, s2>>>();
    dim3 gh((EE + 511) / 512, RR);
    k_hist<<<gh, 512, 0, s2>>>(ei);
    k_scan_a<<<NSB, 256, 0, s2>>>();
    k_scan_c<<<NSB, 256, 0, s2>>>();
    k_scatter<<<gh, 512, 0, s2>>>(ei);
    cudaEventRecord(evJoin, s2);

    // ---- branch A (default stream): GEMM + fused alpha ----
    dim3 gg((NN + BM - 1) / BM, RR);
    k_gemm<<<gg, 256, GEMM_SMEM>>>(x, W, att_src, att_dst);

    // join, then fused aggregation + residual + LayerNorm
    cudaStreamWaitEvent(0, evJoin, 0);
    k_agg<<<(NN * 32 + 255) / 256, 256>>>(x, gamma, beta, out);
}